// round 13
// baseline (speedup 1.0000x reference)
#include <cuda_runtime.h>
#include <cstdint>

// WaveGNN: B=16, N=2048, D=128, L=3
//   per layer: hw = h @ W ; agg = adj^T @ hw ; h = relu(LN(agg + b + h))
// Both GEMMs on tensor cores via generic-target mma.sync tf32 (m16n8k8).
// R13: gcn CTA 64j x 128e, 128 thr (4 warps), NSTG=2, 51.2KB smem
//      -> 4 independent CTAs/SM (barrier decorrelation; RF stays full).

#define BATCH 16
#define NN    2048
#define DD    128

// gcn tiling
#define CTJ   64           // j rows per CTA
#define KC    32           // K (i) rows per pipeline chunk
#define NKC   (NN / KC)    // 64 chunks
#define ASTR  72           // adj tile stride (72 % 32 == 8 -> conflict-free)
#define A_FLOATS (KC * ASTR)          // 2304
#define B_FLOATS (KC * DD)            // 4096 (frag layout, no padding)
#define STG_F (A_FLOATS + B_FLOATS)   // 6400 floats/stage
#define NSTG  2
#define DYN_SMEM (NSTG * STG_F * 4)   // 51200 bytes -> 4 CTAs/SM

// linear tiling
#define LW_STR 136
#define LH_STR 36
#define LW_FLOATS (DD * LW_STR)            // 17408
#define LH_FLOATS (DD * LH_STR)            // 4608 per stage (128 rows x 32+4)
#define DYN_L ((LW_FLOATS + 2 * LH_FLOATS) * 4)   // 106496 bytes

typedef unsigned long long u64;

// ---------------- scratch (static device globals; no runtime alloc) --------
__device__ float g_hw[BATCH * NN * DD];   // B-FRAGMENT layout (see below)
__device__ float g_h0[BATCH * NN * DD];
__device__ float g_h1[BATCH * NN * DD];

// hw fragment layout, per batch b, per 32-row i-chunk c, value hw[i][e]:
//   ic=i%32, kk=ic/8, kr=ic%8, qn=kr&3, h=kr>>2
//   wn=e>>6, nl=e&63, qm=nl&7, nt=nl>>3
//   lane=qm*4+qn, s=nt*2+h, s4=s>>2, sl=s&3, sw=(lane>>1)&3
//   off = (b*64+c)*4096 + (wn*4+kk)*512 + lane*16 + ((s4^sw)<<2) + sl
// One LDS.128 per lane yields (b0,b1) for two consecutive nt.

// ---------------- helpers ---------------------------------------------------
__device__ __forceinline__ uint32_t smem_u32(const void* p) {
    uint32_t a;
    asm("{ .reg .u64 t; cvta.to.shared.u64 t, %1; cvt.u32.u64 %0, t; }"
        : "=r"(a) : "l"(p));
    return a;
}

__device__ __forceinline__ void cpa16(uint32_t dst, const void* src) {
    asm volatile("cp.async.cg.shared.global [%0], [%1], 16;"
                 :: "r"(dst), "l"(src) : "memory");
}
#define CPA_COMMIT() asm volatile("cp.async.commit_group;" ::: "memory")
#define CPA_WAIT1()  asm volatile("cp.async.wait_group 1;" ::: "memory")
#define CPA_WAIT0()  asm volatile("cp.async.wait_group 0;" ::: "memory")

__device__ __forceinline__ void mma_tf32(float* d, const uint32_t* a,
                                         const uint32_t b0, const uint32_t b1) {
    asm volatile(
        "mma.sync.aligned.m16n8k8.row.col.f32.tf32.tf32.f32 "
        "{%0,%1,%2,%3}, {%4,%5,%6,%7}, {%8,%9}, {%0,%1,%2,%3};"
        : "+f"(d[0]), "+f"(d[1]), "+f"(d[2]), "+f"(d[3])
        : "r"(a[0]), "r"(a[1]), "r"(a[2]), "r"(a[3]), "r"(b0), "r"(b1));
}

__device__ __forceinline__ float tf32_rna(float v) {
    uint32_t u;
    asm("cvt.rna.tf32.f32 %0, %1;" : "=r"(u) : "f"(v));
    return __uint_as_float(u);
}

// ---------------------------------------------------------------------------
// linear_mma: hw[m,e] = sum_k h[m,k] * W[k,e]  (tf32 mma, K=128)
// grid 256 x 256 thr; CTA 128m x 128e; warp tile 32x64 (4m x 2n warps).
// Epilogue scatters tf32-rounded results into the B-fragment layout.
// ---------------------------------------------------------------------------
__global__ void __launch_bounds__(256, 2)
linear_mma(const float* __restrict__ h, const float* __restrict__ W,
           float* __restrict__ out) {
    extern __shared__ float lsm[];
    float* Ws_s = lsm;                       // [128][LW_STR]
    float* Hs0 = lsm + LW_FLOATS;            // [128][LH_STR] x2 stages
    float* Hs1 = Hs0 + LH_FLOATS;

    const int tid = threadIdx.x;
    const int lane = tid & 31;
    const int wid = tid >> 5;
    const int warp_m = wid & 3;
    const int warp_n = wid >> 2;
    const int qm = lane >> 2;
    const int qn = lane & 3;
    const int m0 = blockIdx.x * 128;
    const uint32_t smem_b = smem_u32(lsm);

    // h chunk loader: 128 rows x 32 k-floats into Hs[stage]
    const float* h_src = h + (size_t)(m0 + (tid >> 3)) * DD + (tid & 7) * 4;
    uint32_t h_doff = ((tid >> 3) * LH_STR + (tid & 7) * 4) * 4;
    auto load_h = [&](int kt, int st) {
        uint32_t base = smem_b + (uint32_t)(LW_FLOATS + st * LH_FLOATS) * 4 + h_doff;
        const float* src = h_src + kt * KC;
#pragma unroll
        for (int p = 0; p < 4; p++)
            cpa16(base + (uint32_t)(p * 32 * LH_STR) * 4, src + (size_t)(p * 32) * DD);
        CPA_COMMIT();
    };

    load_h(0, 0);
    load_h(1, 1);

    // preload W (tf32-rna rounded)
#pragma unroll
    for (int p = 0; p < 16; p++) {
        int v = tid + p * 256;
        int k = v >> 5, e4 = (v & 31) * 4;
        float4 w = *(const float4*)(W + (size_t)k * DD + e4);
        float* dst = Ws_s + k * LW_STR + e4;
        dst[0] = tf32_rna(w.x);
        dst[1] = tf32_rna(w.y);
        dst[2] = tf32_rna(w.z);
        dst[3] = tf32_rna(w.w);
    }

    float d[2][8][4];
#pragma unroll
    for (int mt = 0; mt < 2; mt++)
#pragma unroll
        for (int nt = 0; nt < 8; nt++)
#pragma unroll
            for (int c = 0; c < 4; c++) d[mt][nt][c] = 0.f;

    CPA_WAIT1();
    __syncthreads();

    const uint32_t* Wu = (const uint32_t*)Ws_s;

    for (int kt = 0; kt < 4; kt++) {
        const uint32_t* Hu = (const uint32_t*)((kt & 1) ? Hs1 : Hs0);
#pragma unroll
        for (int kk = 0; kk < 4; kk++) {
            const uint32_t* ap = Hu + (warp_m * 32 + qm) * LH_STR + kk * 8 + qn;
            uint32_t af0[4] = {ap[0], ap[8 * LH_STR], ap[4], ap[8 * LH_STR + 4]};
            const uint32_t* ap1 = ap + 16 * LH_STR;
            uint32_t af1[4] = {ap1[0], ap1[8 * LH_STR], ap1[4], ap1[8 * LH_STR + 4]};

            const uint32_t* bp = Wu + (kt * KC + kk * 8 + qn) * LW_STR +
                                 warp_n * 64 + qm;
#pragma unroll
            for (int nt = 0; nt < 8; nt++) {
                uint32_t b0 = bp[nt * 8];
                uint32_t b1 = bp[4 * LW_STR + nt * 8];
                mma_tf32(d[0][nt], af0, b0, b1);
                mma_tf32(d[1][nt], af1, b0, b1);
            }
        }
        if (kt + 2 < 4) {
            __syncthreads();            // all warps done reading stage kt&1
            load_h(kt + 2, kt & 1);
            CPA_WAIT1();                // chunk kt+1 landed (own copies)
            __syncthreads();            // ... and everyone else's
        } else if (kt + 1 < 4) {
            CPA_WAIT0();                // last chunk's copies (own)
            __syncthreads();            // make peers' copies visible
        }
    }

    // ---- epilogue: scatter tf32-rounded into B-fragment layout ------------
    const int bb = m0 >> 11;                   // batch (128 | 2048)
#pragma unroll
    for (int mt = 0; mt < 2; mt++)
#pragma unroll
        for (int hh = 0; hh < 2; hh++) {
            int i_glob = m0 + warp_m * 32 + mt * 16 + hh * 8 + qm;
            int il = i_glob & (NN - 1);
            int chunk = il >> 5;
            int ic = il & 31;
            int kko = ic >> 3;
            int kr = ic & 7;
            int qi = kr & 3;
            int hi = kr >> 2;
            size_t cbase = ((size_t)(bb * 64 + chunk)) * 4096 +
                           (size_t)((warp_n * 4 + kko) * 512);
#pragma unroll
            for (int cl = 0; cl < 2; cl++) {
                int lane_ = (qn * 2 + cl) * 4 + qi;
                int sw_ = (lane_ >> 1) & 3;
                size_t lbase = cbase + lane_ * 16;
#pragma unroll
                for (int nt = 0; nt < 8; nt++) {
                    int s = nt * 2 + hi;
                    int s4 = s >> 2, sl = s & 3;
                    out[lbase + ((s4 ^ sw_) << 2) + sl] =
                        tf32_rna(d[mt][nt][hh * 2 + cl]);
                }
            }
        }
}

// ---------------------------------------------------------------------------
// gcn_kernel (tf32 mma.sync):
//   D[j,e] = sum_i adj[b,i,j] * hw[b,i,e]
//   out = relu(LN(D + bias + hin))
// grid (NN/CTJ=32, BATCH) x 128 threads; 4 warps, warp tile 32x64 (2m x 2n)
// 4 independent CTAs per SM.
// ---------------------------------------------------------------------------
__global__ void __launch_bounds__(128, 4)
gcn_kernel(const float* __restrict__ adj, const float* __restrict__ hw,
           const float* __restrict__ hin, float* __restrict__ hout,
           const float* __restrict__ bias, const float* __restrict__ gamma,
           const float* __restrict__ beta) {
    extern __shared__ float smem[];
    __shared__ float red_s[CTJ][2][2];
    __shared__ float bias_s[DD], gamma_s[DD], beta_s[DD];

    const int tid = threadIdx.x;
    const int lane = tid & 31;
    const int wid = tid >> 5;
    const int warp_m = wid & 1;      // 2 m-warps x 32 rows
    const int warp_n = wid >> 1;     // 2 n-warps x 64 cols
    const int qm = lane >> 2;        // 0..7
    const int qn = lane & 3;         // 0..3
    const int sw = (lane >> 1) & 3;  // B-frag xor swizzle
    const int b = blockIdx.y;
    const int j0 = blockIdx.x * CTJ;

    bias_s[tid] = bias[tid & (DD - 1)];
    gamma_s[tid] = gamma[tid & (DD - 1)];
    beta_s[tid] = beta[tid & (DD - 1)];

    const uint32_t smem_b = smem_u32(smem);

    float d[2][8][4];
#pragma unroll
    for (int mt = 0; mt < 2; mt++)
#pragma unroll
        for (int nt = 0; nt < 8; nt++)
#pragma unroll
            for (int c = 0; c < 4; c++) d[mt][nt][c] = 0.f;

    // ---- chunk loader: all addressing hoisted into incrementing regs ------
    // A: 32 rows x 64 j-cols. 128 threads: t -> row=t>>4, col4=(t&15)*4
    // B: contiguous 16KB fragment slab
    const float* a_src = adj + (size_t)b * NN * NN + (size_t)(tid >> 4) * NN +
                         j0 + (tid & 15) * 4;
    const float* b_src = hw + (size_t)b * NN * DD + tid * 4;
    const uint32_t a_doff = (uint32_t)((tid >> 4) * ASTR + (tid & 15) * 4) * 4;
    const uint32_t b_doff = (uint32_t)tid * 16;

    auto load_chunk = [&](int st) {
        uint32_t a_base = smem_b + (uint32_t)(st * STG_F) * 4 + a_doff;
        uint32_t b_base = smem_b + (uint32_t)(st * STG_F + A_FLOATS) * 4 + b_doff;
#pragma unroll
        for (int p = 0; p < 4; p++)
            cpa16(a_base + (uint32_t)(p * 8 * ASTR) * 4, a_src + (size_t)(p * 8) * NN);
#pragma unroll
        for (int p = 0; p < 8; p++)
            cpa16(b_base + (uint32_t)(p * 2048), b_src + p * 512);
        CPA_COMMIT();
        a_src += (size_t)KC * NN;
        b_src += B_FLOATS;
    };

    load_chunk(0);
    load_chunk(1);

    int cs = 0;
    for (int kt = 0; kt < NKC; kt++) {
        CPA_WAIT1();
        __syncthreads();

        const float* As = smem + cs * STG_F;
        const float* Bs = As + A_FLOATS;
        const uint32_t* Asu = (const uint32_t*)As;

#pragma unroll
        for (int kk = 0; kk < KC / 8; kk++) {
            const uint32_t* ap = Asu + (kk * 8 + qn) * ASTR + warp_m * 32 + qm;
            uint32_t af0[4] = {ap[0], ap[8], ap[4 * ASTR], ap[4 * ASTR + 8]};
            uint32_t af1[4] = {ap[16], ap[24], ap[4 * ASTR + 16], ap[4 * ASTR + 24]};

            const float4* bp = (const float4*)(Bs + (warp_n * 4 + kk) * 512) +
                               lane * 4;
#pragma unroll
            for (int i = 0; i < 4; i++) {
                float4 bq = bp[i ^ sw];
                uint32_t b0 = __float_as_uint(bq.x);
                uint32_t b1 = __float_as_uint(bq.y);
                uint32_t b2 = __float_as_uint(bq.z);
                uint32_t b3 = __float_as_uint(bq.w);
                mma_tf32(d[0][2 * i + 0], af0, b0, b1);
                mma_tf32(d[0][2 * i + 1], af0, b2, b3);
                mma_tf32(d[1][2 * i + 0], af1, b0, b1);
                mma_tf32(d[1][2 * i + 1], af1, b2, b3);
            }
        }

        __syncthreads();                 // all warps done reading stage cs
        if (kt + 2 < NKC) load_chunk(cs);
        cs ^= 1;
    }
    CPA_WAIT0();

    // ---- epilogue: z = D + bias + res ; LN ; relu ; store -----------------
    const float* hin_b = hin + ((size_t)b * NN + j0) * DD;
    float* hout_b = hout + ((size_t)b * NN + j0) * DD;

#pragma unroll
    for (int mt = 0; mt < 2; mt++)
#pragma unroll
        for (int h = 0; h < 2; h++) {
            int jl = warp_m * 32 + mt * 16 + h * 8 + qm;
            const float* rrow = hin_b + (size_t)jl * DD;
            float s = 0.f, q = 0.f;
#pragma unroll
            for (int nt = 0; nt < 8; nt++) {
                int e = warp_n * 64 + nt * 8 + qn * 2;
                float2 rv = *(const float2*)(rrow + e);
                float z0 = d[mt][nt][2 * h + 0] + bias_s[e + 0] + rv.x;
                float z1 = d[mt][nt][2 * h + 1] + bias_s[e + 1] + rv.y;
                d[mt][nt][2 * h + 0] = z0;
                d[mt][nt][2 * h + 1] = z1;
                s += z0 + z1;
                q += z0 * z0 + z1 * z1;
            }
            s += __shfl_xor_sync(0xffffffffu, s, 1);
            s += __shfl_xor_sync(0xffffffffu, s, 2);
            q += __shfl_xor_sync(0xffffffffu, q, 1);
            q += __shfl_xor_sync(0xffffffffu, q, 2);
            if (qn == 0) {
                red_s[jl][warp_n][0] = s;
                red_s[jl][warp_n][1] = q;
            }
        }
    __syncthreads();

#pragma unroll
    for (int mt = 0; mt < 2; mt++)
#pragma unroll
        for (int h = 0; h < 2; h++) {
            int jl = warp_m * 32 + mt * 16 + h * 8 + qm;
            float s = red_s[jl][0][0] + red_s[jl][1][0];
            float q = red_s[jl][0][1] + red_s[jl][1][1];
            float mu = s * (1.0f / DD);
            float var = q * (1.0f / DD) - mu * mu;
            float rstd = rsqrtf(var + 1e-5f);
            float* orow = hout_b + (size_t)jl * DD;
#pragma unroll
            for (int nt = 0; nt < 8; nt++) {
                int e = warp_n * 64 + nt * 8 + qn * 2;
                float2 o;
                o.x = fmaxf(0.f, (d[mt][nt][2 * h + 0] - mu) * rstd * gamma_s[e + 0] + beta_s[e + 0]);
                o.y = fmaxf(0.f, (d[mt][nt][2 * h + 1] - mu) * rstd * gamma_s[e + 1] + beta_s[e + 1]);
                *(float2*)(orow + e) = o;
            }
        }
}

// ---------------------------------------------------------------------------
extern "C" void kernel_launch(void* const* d_in, const int* in_sizes, int n_in,
                              void* d_out, int out_size) {
    (void)in_sizes; (void)n_in; (void)out_size;
    const float* X      = (const float*)d_in[0];
    const float* adj    = (const float*)d_in[1];
    const float* Ws     = (const float*)d_in[2];
    const float* bs     = (const float*)d_in[3];
    const float* gammas = (const float*)d_in[4];
    const float* betas  = (const float*)d_in[5];
    float* out = (float*)d_out;

    float *hw, *h0, *h1;
    cudaGetSymbolAddress((void**)&hw, g_hw);
    cudaGetSymbolAddress((void**)&h0, g_h0);
    cudaGetSymbolAddress((void**)&h1, g_h1);

    static int configured = 0;
    if (!configured) {
        cudaFuncSetAttribute(gcn_kernel,
                             cudaFuncAttributeMaxDynamicSharedMemorySize,
                             DYN_SMEM);
        cudaFuncSetAttribute(linear_mma,
                             cudaFuncAttributeMaxDynamicSharedMemorySize,
                             DYN_L);
        configured = 1;
    }

    const float* hsrc = X;
    for (int l = 0; l < 3; l++) {
        float* hdst = (l == 2) ? out : (l == 0 ? h0 : h1);
        linear_mma<<<(BATCH * NN) / 128, 256, DYN_L>>>(
            hsrc, Ws + (size_t)l * DD * DD, hw);
        gcn_kernel<<<dim3(NN / CTJ, BATCH), 128, DYN_SMEM>>>(
            adj, hw, hsrc, hdst,
            bs + (size_t)l * DD, gammas + (size_t)l * DD,
            betas + (size_t)l * DD);
        hsrc = hdst;
    }
}

// round 16
// speedup vs baseline: 1.5303x; 1.5303x over previous
#include <cuda_runtime.h>
#include <cstdint>

// WaveGNN: B=16, N=2048, D=128, L=3
//   per layer: hw = h @ W ; agg = adj^T @ hw ; h = relu(LN(agg + b + h))
// Both GEMMs on tensor cores via generic-target mma.sync tf32 (m16n8k8).
// R14: revert to R12 shape (CTJ=128, 8 warps, 2 CTAs/SM, NSTG=3);
//      + gcn B-fragment double-buffering across kk (hide LDS latency)
//      + linear coalesced epilogue via smem staging (contiguous 64KB region).

#define BATCH 16
#define NN    2048
#define DD    128

// gcn tiling
#define CTJ   128          // j rows per CTA
#define KC    32           // K (i) rows per pipeline chunk
#define NKC   (NN / KC)    // 64 chunks
#define ASTR  136          // adj tile stride (8qn+qm distinct banks)
#define A_FLOATS (KC * ASTR)          // 4352
#define B_FLOATS (KC * DD)            // 4096 (frag layout, no padding)
#define STG_F (A_FLOATS + B_FLOATS)   // 8448 floats/stage
#define NSTG  3
#define DYN_SMEM (NSTG * STG_F * 4)   // 101376 bytes -> 2 CTAs/SM

// linear tiling
#define LW_STR 136
#define LH_STR 36
#define LW_FLOATS (DD * LW_STR)            // 17408
#define LH_FLOATS (DD * LH_STR)            // 4608 per stage (128 rows x 32+4)
#define DYN_L ((LW_FLOATS + 2 * LH_FLOATS) * 4)   // 106496 bytes

typedef unsigned long long u64;

// ---------------- scratch (static device globals; no runtime alloc) --------
__device__ float g_hw[BATCH * NN * DD];   // B-FRAGMENT layout (see below)
__device__ float g_h0[BATCH * NN * DD];
__device__ float g_h1[BATCH * NN * DD];

// hw fragment layout, per batch b, per 32-row i-chunk c, value hw[i][e]:
//   ic=i%32, kk=ic/8, kr=ic%8, qn=kr&3, h=kr>>2
//   wn=e>>6, nl=e&63, qm=nl&7, nt=nl>>3
//   lane=qm*4+qn, s=nt*2+h, s4=s>>2, sl=s&3, sw=(lane>>1)&3
//   off = (b*64+c)*4096 + (wn*4+kk)*512 + lane*16 + ((s4^sw)<<2) + sl
// One LDS.128 per lane yields (b0,b1) for two consecutive nt.

// ---------------- helpers ---------------------------------------------------
__device__ __forceinline__ uint32_t smem_u32(const void* p) {
    uint32_t a;
    asm("{ .reg .u64 t; cvta.to.shared.u64 t, %1; cvt.u32.u64 %0, t; }"
        : "=r"(a) : "l"(p));
    return a;
}

__device__ __forceinline__ void cpa16(uint32_t dst, const void* src) {
    asm volatile("cp.async.cg.shared.global [%0], [%1], 16;"
                 :: "r"(dst), "l"(src) : "memory");
}
#define CPA_COMMIT() asm volatile("cp.async.commit_group;" ::: "memory")
#define CPA_WAIT1()  asm volatile("cp.async.wait_group 1;" ::: "memory")
#define CPA_WAIT0()  asm volatile("cp.async.wait_group 0;" ::: "memory")

__device__ __forceinline__ void mma_tf32(float* d, const uint32_t* a,
                                         const uint32_t b0, const uint32_t b1) {
    asm volatile(
        "mma.sync.aligned.m16n8k8.row.col.f32.tf32.tf32.f32 "
        "{%0,%1,%2,%3}, {%4,%5,%6,%7}, {%8,%9}, {%0,%1,%2,%3};"
        : "+f"(d[0]), "+f"(d[1]), "+f"(d[2]), "+f"(d[3])
        : "r"(a[0]), "r"(a[1]), "r"(a[2]), "r"(a[3]), "r"(b0), "r"(b1));
}

__device__ __forceinline__ float tf32_rna(float v) {
    uint32_t u;
    asm("cvt.rna.tf32.f32 %0, %1;" : "=r"(u) : "f"(v));
    return __uint_as_float(u);
}

// ---------------------------------------------------------------------------
// linear_mma: hw[m,e] = sum_k h[m,k] * W[k,e]  (tf32 mma, K=128)
// grid 256 x 256 thr; CTA 128m x 128e; warp tile 32x64 (4m x 2n warps).
// Epilogue stages fragments in smem, then writes the CTA's contiguous
// 64KB fragment-layout region with coalesced STG.128.
// ---------------------------------------------------------------------------
__global__ void __launch_bounds__(256, 2)
linear_mma(const float* __restrict__ h, const float* __restrict__ W,
           float* __restrict__ out) {
    extern __shared__ float lsm[];
    float* Ws_s = lsm;                       // [128][LW_STR]
    float* Hs0 = lsm + LW_FLOATS;            // [128][LH_STR] x2 stages
    float* Hs1 = Hs0 + LH_FLOATS;

    const int tid = threadIdx.x;
    const int lane = tid & 31;
    const int wid = tid >> 5;
    const int warp_m = wid & 3;
    const int warp_n = wid >> 2;
    const int qm = lane >> 2;
    const int qn = lane & 3;
    const int m0 = blockIdx.x * 128;
    const uint32_t smem_b = smem_u32(lsm);

    // h chunk loader: 128 rows x 32 k-floats into Hs[stage]
    const float* h_src = h + (size_t)(m0 + (tid >> 3)) * DD + (tid & 7) * 4;
    uint32_t h_doff = ((tid >> 3) * LH_STR + (tid & 7) * 4) * 4;
    auto load_h = [&](int kt, int st) {
        uint32_t base = smem_b + (uint32_t)(LW_FLOATS + st * LH_FLOATS) * 4 + h_doff;
        const float* src = h_src + kt * KC;
#pragma unroll
        for (int p = 0; p < 4; p++)
            cpa16(base + (uint32_t)(p * 32 * LH_STR) * 4, src + (size_t)(p * 32) * DD);
        CPA_COMMIT();
    };

    load_h(0, 0);
    load_h(1, 1);

    // preload W (tf32-rna rounded)
#pragma unroll
    for (int p = 0; p < 16; p++) {
        int v = tid + p * 256;
        int k = v >> 5, e4 = (v & 31) * 4;
        float4 w = *(const float4*)(W + (size_t)k * DD + e4);
        float* dst = Ws_s + k * LW_STR + e4;
        dst[0] = tf32_rna(w.x);
        dst[1] = tf32_rna(w.y);
        dst[2] = tf32_rna(w.z);
        dst[3] = tf32_rna(w.w);
    }

    float d[2][8][4];
#pragma unroll
    for (int mt = 0; mt < 2; mt++)
#pragma unroll
        for (int nt = 0; nt < 8; nt++)
#pragma unroll
            for (int c = 0; c < 4; c++) d[mt][nt][c] = 0.f;

    CPA_WAIT1();
    __syncthreads();

    const uint32_t* Wu = (const uint32_t*)Ws_s;

    for (int kt = 0; kt < 4; kt++) {
        const uint32_t* Hu = (const uint32_t*)((kt & 1) ? Hs1 : Hs0);
#pragma unroll
        for (int kk = 0; kk < 4; kk++) {
            const uint32_t* ap = Hu + (warp_m * 32 + qm) * LH_STR + kk * 8 + qn;
            uint32_t af0[4] = {ap[0], ap[8 * LH_STR], ap[4], ap[8 * LH_STR + 4]};
            const uint32_t* ap1 = ap + 16 * LH_STR;
            uint32_t af1[4] = {ap1[0], ap1[8 * LH_STR], ap1[4], ap1[8 * LH_STR + 4]};

            const uint32_t* bp = Wu + (kt * KC + kk * 8 + qn) * LW_STR +
                                 warp_n * 64 + qm;
#pragma unroll
            for (int nt = 0; nt < 8; nt++) {
                uint32_t b0 = bp[nt * 8];
                uint32_t b1 = bp[4 * LW_STR + nt * 8];
                mma_tf32(d[0][nt], af0, b0, b1);
                mma_tf32(d[1][nt], af1, b0, b1);
            }
        }
        if (kt + 2 < 4) {
            __syncthreads();            // all warps done reading stage kt&1
            load_h(kt + 2, kt & 1);
            CPA_WAIT1();                // chunk kt+1 landed (own copies)
            __syncthreads();            // ... and everyone else's
        } else if (kt + 1 < 4) {
            CPA_WAIT0();                // last chunk's copies (own)
            __syncthreads();            // make peers' copies visible
        }
    }

    // ---- epilogue: stage fragments in smem, then coalesced STG.128 --------
    __syncthreads();                    // mainloop smem reads complete
    float* stage = lsm;                 // 16384 floats = 64KB
    const int bb = m0 >> 11;            // batch (m0 / NN)
    const int chunk0 = (m0 & (NN - 1)) >> 5;
    const size_t G0 = ((size_t)(bb * 64 + chunk0)) * 4096;

#pragma unroll
    for (int mt = 0; mt < 2; mt++)
#pragma unroll
        for (int hh = 0; hh < 2; hh++) {
            int i_glob = m0 + warp_m * 32 + mt * 16 + hh * 8 + qm;
            int il = i_glob & (NN - 1);
            int chunk = il >> 5;
            int ic = il & 31;
            int kko = ic >> 3;
            int kr = ic & 7;
            int qi = kr & 3;
            int hi = kr >> 2;
            uint32_t cbase = (uint32_t)((chunk - chunk0) * 4096 +
                                        (warp_n * 4 + kko) * 512);
#pragma unroll
            for (int cl = 0; cl < 2; cl++) {
                int lane_ = (qn * 2 + cl) * 4 + qi;
                int sw_ = (lane_ >> 1) & 3;
                uint32_t lbase = cbase + lane_ * 16;
#pragma unroll
                for (int nt = 0; nt < 8; nt++) {
                    int s = nt * 2 + hi;
                    int s4 = s >> 2, sl = s & 3;
                    stage[lbase + ((s4 ^ sw_) << 2) + sl] =
                        tf32_rna(d[mt][nt][hh * 2 + cl]);
                }
            }
        }
    __syncthreads();

    float4* gdst = (float4*)(out + G0);
    const float4* ssrc = (const float4*)stage;
#pragma unroll
    for (int p = 0; p < 16; p++)
        gdst[tid + p * 256] = ssrc[tid + p * 256];
}

// ---------------------------------------------------------------------------
// gcn_kernel (tf32 mma.sync):
//   D[j,e] = sum_i adj[b,i,j] * hw[b,i,e]
//   out = relu(LN(D + bias + hin))
// grid (NN/CTJ=16, BATCH) x 256 threads; 8 warps, warp tile 32x64 (4m x 2n)
// B fragments double-buffered across kk to hide LDS latency.
// ---------------------------------------------------------------------------
__global__ void __launch_bounds__(256, 2)
gcn_kernel(const float* __restrict__ adj, const float* __restrict__ hw,
           const float* __restrict__ hin, float* __restrict__ hout,
           const float* __restrict__ bias, const float* __restrict__ gamma,
           const float* __restrict__ beta) {
    extern __shared__ float smem[];
    __shared__ float red_s[CTJ][2][2];
    __shared__ float bias_s[DD], gamma_s[DD], beta_s[DD];

    const int tid = threadIdx.x;
    const int lane = tid & 31;
    const int wid = tid >> 5;
    const int warp_m = wid & 3;      // 4 m-warps x 32 rows
    const int warp_n = wid >> 2;     // 2 n-warps x 64 cols
    const int qm = lane >> 2;        // 0..7
    const int qn = lane & 3;         // 0..3
    const int sw = (lane >> 1) & 3;  // B-frag xor swizzle
    const int b = blockIdx.y;
    const int j0 = blockIdx.x * CTJ;

    if (tid < DD) {
        bias_s[tid] = bias[tid];
        gamma_s[tid] = gamma[tid];
        beta_s[tid] = beta[tid];
    }

    const uint32_t smem_b = smem_u32(smem);

    float d[2][8][4];
#pragma unroll
    for (int mt = 0; mt < 2; mt++)
#pragma unroll
        for (int nt = 0; nt < 8; nt++)
#pragma unroll
            for (int c = 0; c < 4; c++) d[mt][nt][c] = 0.f;

    // ---- chunk loader: all addressing hoisted into incrementing regs ------
    const float* a_src = adj + (size_t)b * NN * NN + (size_t)(tid >> 5) * NN +
                         j0 + (tid & 31) * 4;
    const float* b_src = hw + (size_t)b * NN * DD + tid * 4;
    const uint32_t a_doff = (uint32_t)((tid >> 5) * ASTR + (tid & 31) * 4) * 4;
    const uint32_t b_doff = (uint32_t)tid * 16;

    auto load_chunk = [&](int st) {
        uint32_t a_base = smem_b + (uint32_t)(st * STG_F) * 4 + a_doff;
        uint32_t b_base = smem_b + (uint32_t)(st * STG_F + A_FLOATS) * 4 + b_doff;
#pragma unroll
        for (int p = 0; p < 4; p++)
            cpa16(a_base + (uint32_t)(p * 8 * ASTR) * 4, a_src + (size_t)(p * 8) * NN);
#pragma unroll
        for (int p = 0; p < 4; p++)
            cpa16(b_base + (uint32_t)(p * 4096), b_src + p * 1024);
        CPA_COMMIT();
        a_src += (size_t)KC * NN;
        b_src += B_FLOATS;
    };

    load_chunk(0);
    load_chunk(1);

    int cs = 0, ls = 2;
    for (int kt = 0; kt < NKC; kt++) {
        CPA_WAIT1();
        __syncthreads();
        if (kt + 2 < NKC) {
            load_chunk(ls);
            ls = (ls == NSTG - 1) ? 0 : ls + 1;
        }

        const float* As = smem + cs * STG_F;
        const float* Bs = As + A_FLOATS;
        cs = (cs == NSTG - 1) ? 0 : cs + 1;
        const uint32_t* Asu = (const uint32_t*)As;
        const float4* Bs4 = (const float4*)(Bs + warp_n * 4 * 512) + lane * 4;

        // preload kk=0 B fragments
        float4 bq[2][4];
        bq[0][0] = Bs4[0 ^ sw];
        bq[0][1] = Bs4[1 ^ sw];
        bq[0][2] = Bs4[2 ^ sw];
        bq[0][3] = Bs4[3 ^ sw];

#pragma unroll
        for (int kk = 0; kk < KC / 8; kk++) {
            const int cur = kk & 1;
            if (kk + 1 < KC / 8) {                 // prefetch next kk's B
                const float4* bp = Bs4 + (kk + 1) * 128;
                bq[cur ^ 1][0] = bp[0 ^ sw];
                bq[cur ^ 1][1] = bp[1 ^ sw];
                bq[cur ^ 1][2] = bp[2 ^ sw];
                bq[cur ^ 1][3] = bp[3 ^ sw];
            }
            const uint32_t* ap = Asu + (kk * 8 + qn) * ASTR + warp_m * 32 + qm;
            uint32_t af0[4] = {ap[0], ap[8], ap[4 * ASTR], ap[4 * ASTR + 8]};
            uint32_t af1[4] = {ap[16], ap[24], ap[4 * ASTR + 16], ap[4 * ASTR + 24]};
#pragma unroll
            for (int i = 0; i < 4; i++) {
                float4 q = bq[cur][i];
                uint32_t b0 = __float_as_uint(q.x);
                uint32_t b1 = __float_as_uint(q.y);
                uint32_t b2 = __float_as_uint(q.z);
                uint32_t b3 = __float_as_uint(q.w);
                mma_tf32(d[0][2 * i + 0], af0, b0, b1);
                mma_tf32(d[0][2 * i + 1], af0, b2, b3);
                mma_tf32(d[1][2 * i + 0], af1, b0, b1);
                mma_tf32(d[1][2 * i + 1], af1, b2, b3);
            }
        }
    }
    CPA_WAIT0();

    // ---- epilogue: z = D + bias + res ; LN ; relu ; store -----------------
    const float* hin_b = hin + ((size_t)b * NN + j0) * DD;
    float* hout_b = hout + ((size_t)b * NN + j0) * DD;

#pragma unroll
    for (int mt = 0; mt < 2; mt++)
#pragma unroll
        for (int h = 0; h < 2; h++) {
            int jl = warp_m * 32 + mt * 16 + h * 8 + qm;
            const float* rrow = hin_b + (size_t)jl * DD;
            float s = 0.f, q = 0.f;
#pragma unroll
            for (int nt = 0; nt < 8; nt++) {
                int e = warp_n * 64 + nt * 8 + qn * 2;
                float2 rv = *(const float2*)(rrow + e);
                float z0 = d[mt][nt][2 * h + 0] + bias_s[e + 0] + rv.x;
                float z1 = d[mt][nt][2 * h + 1] + bias_s[e + 1] + rv.y;
                d[mt][nt][2 * h + 0] = z0;
                d[mt][nt][2 * h + 1] = z1;
                s += z0 + z1;
                q += z0 * z0 + z1 * z1;
            }
            s += __shfl_xor_sync(0xffffffffu, s, 1);
            s += __shfl_xor_sync(0xffffffffu, s, 2);
            q += __shfl_xor_sync(0xffffffffu, q, 1);
            q += __shfl_xor_sync(0xffffffffu, q, 2);
            if (qn == 0) {
                red_s[jl][warp_n][0] = s;
                red_s[jl][warp_n][1] = q;
            }
        }
    __syncthreads();

#pragma unroll
    for (int mt = 0; mt < 2; mt++)
#pragma unroll
        for (int h = 0; h < 2; h++) {
            int jl = warp_m * 32 + mt * 16 + h * 8 + qm;
            float s = red_s[jl][0][0] + red_s[jl][1][0];
            float q = red_s[jl][0][1] + red_s[jl][1][1];
            float mu = s * (1.0f / DD);
            float var = q * (1.0f / DD) - mu * mu;
            float rstd = rsqrtf(var + 1e-5f);
            float* orow = hout_b + (size_t)jl * DD;
#pragma unroll
            for (int nt = 0; nt < 8; nt++) {
                int e = warp_n * 64 + nt * 8 + qn * 2;
                float2 o;
                o.x = fmaxf(0.f, (d[mt][nt][2 * h + 0] - mu) * rstd * gamma_s[e + 0] + beta_s[e + 0]);
                o.y = fmaxf(0.f, (d[mt][nt][2 * h + 1] - mu) * rstd * gamma_s[e + 1] + beta_s[e + 1]);
                *(float2*)(orow + e) = o;
            }
        }
}

// ---------------------------------------------------------------------------
extern "C" void kernel_launch(void* const* d_in, const int* in_sizes, int n_in,
                              void* d_out, int out_size) {
    (void)in_sizes; (void)n_in; (void)out_size;
    const float* X      = (const float*)d_in[0];
    const float* adj    = (const float*)d_in[1];
    const float* Ws     = (const float*)d_in[2];
    const float* bs     = (const float*)d_in[3];
    const float* gammas = (const float*)d_in[4];
    const float* betas  = (const float*)d_in[5];
    float* out = (float*)d_out;

    float *hw, *h0, *h1;
    cudaGetSymbolAddress((void**)&hw, g_hw);
    cudaGetSymbolAddress((void**)&h0, g_h0);
    cudaGetSymbolAddress((void**)&h1, g_h1);

    static int configured = 0;
    if (!configured) {
        cudaFuncSetAttribute(gcn_kernel,
                             cudaFuncAttributeMaxDynamicSharedMemorySize,
                             DYN_SMEM);
        cudaFuncSetAttribute(linear_mma,
                             cudaFuncAttributeMaxDynamicSharedMemorySize,
                             DYN_L);
        configured = 1;
    }

    const float* hsrc = X;
    for (int l = 0; l < 3; l++) {
        float* hdst = (l == 2) ? out : (l == 0 ? h0 : h1);
        linear_mma<<<(BATCH * NN) / 128, 256, DYN_L>>>(
            hsrc, Ws + (size_t)l * DD * DD, hw);
        gcn_kernel<<<dim3(NN / CTJ, BATCH), 256, DYN_SMEM>>>(
            adj, hw, hsrc, hdst,
            bs + (size_t)l * DD, gammas + (size_t)l * DD,
            betas + (size_t)l * DD);
        hsrc = hdst;
    }
}